// round 10
// baseline (speedup 1.0000x reference)
#include <cuda_runtime.h>

// ---------------------------------------------------------------------------
// AutoregressiveGRUWithAttention  (B=1024, L=64, T=128, IN=13, H=64, OUT=13)
//
// R9: 128 blocks x 256 threads; j = tid>>2 (channel), g = tid&3 (K-quarter
// group, in LANE bits so cross-group reduction is shfl_xor). All weights
// register-resident as quarter rows (f32x2 pairs) -> zero weight smem traffic
// (R7's measured bottleneck). Each thread computes quarter-K gate partials for
// all 8 batches; 2-round butterfly (xor1, xor2) completes the dots; thread g
// owns batches {g, g+4}. h double-buffered (1 sync/enc step, 2/dec step).
// Online-softmax attention (validated in R7/R8).
// ---------------------------------------------------------------------------

typedef unsigned long long ull;

namespace {
constexpr int L_   = 64;
constexpr int T_   = 128;
constexpr int IN_  = 13;
constexpr int H_   = 64;
constexpr int OUT_ = 13;
constexpr int NB_  = 8;
constexpr int THREADS_ = 256;
constexpr int BLOCKS_  = 128;
constexpr int WP_  = 72;             // h/o row stride: conflict-free writes
constexpr int XT_  = 16;             // padded x stride per timestep
constexpr int XPB_ = L_ * XT_;       // 1024 floats per batch

constexpr int SM_H0  = 0;                    // [8][72] ping
constexpr int SM_H1  = SM_H0 + NB_ * WP_;    // [8][72] pong
constexpr int SM_O   = SM_H1 + NB_ * WP_;    // [8][72]
constexpr int SM_NIN = SM_O  + NB_ * WP_;    // [8][16]
constexpr int SM_X   = SM_NIN + NB_ * 16;    // [8][1024]
constexpr int SM_FLOATS = SM_X + NB_ * XPB_; // 10048 floats = 40.2 KB
}

__device__ __forceinline__ ull fma2_(ull a, ull b, ull c) {
    ull d;
    asm("fma.rn.f32x2 %0, %1, %2, %3;" : "=l"(d) : "l"(a), "l"(b), "l"(c));
    return d;
}
__device__ __forceinline__ float hsum2_(ull a) {
    unsigned lo, hi;
    asm("mov.b64 {%0, %1}, %2;" : "=r"(lo), "=r"(hi) : "l"(a));
    return __uint_as_float(lo) + __uint_as_float(hi);
}
__device__ __forceinline__ float sigmoid_(float a) {
    return __fdividef(1.f, 1.f + __expf(-a));
}
__device__ __forceinline__ float tanh_(float a) {
    float c  = fminf(fmaxf(a, -15.f), 15.f);
    float e2 = __expf(2.f * c);
    return __fdividef(e2 - 1.f, e2 + 1.f);
}

// Sum quarter-partials across the 4-lane g-cluster. After this, thread g holds
// the full sum in A[g] and A[g+4] (other entries: partial garbage, unused).
// Round 2 is split by lane parity; xor-2 partners share lane bit0, so each
// masked shfl is executed by exactly the lanes named in its mask.
__device__ __forceinline__ void reduce8_(float (&A)[8], int g) {
    #pragma unroll
    for (int b = 0; b < 8; ++b)
        A[b] += __shfl_xor_sync(0xFFFFFFFFu, A[b], 1);
    #pragma unroll
    for (int b = 0; b < 8; ++b) {
        if ((b & 1) == (g & 1)) {
            unsigned mask = (b & 1) ? 0xAAAAAAAAu : 0x55555555u;
            A[b] += __shfl_xor_sync(mask, A[b], 2);
        }
    }
}

__global__ void __launch_bounds__(THREADS_, 1)
gru_attn_kernel(const float* __restrict__ x, const int* __restrict__ lengths,
                const float* __restrict__ Wih, const float* __restrict__ Whh,
                const float* __restrict__ bih, const float* __restrict__ bhh,
                const float* __restrict__ Wf,  const float* __restrict__ bf,
                const float* __restrict__ Wa,  const float* __restrict__ ba,
                float* __restrict__ out)
{
    __shared__ __align__(16) float sm[SM_FLOATS];
    float* h0   = sm + SM_H0;
    float* h1   = sm + SM_H1;
    float* so   = sm + SM_O;
    float* snin = sm + SM_NIN;
    float* sx   = sm + SM_X;

    const int tid = threadIdx.x;
    const int j   = tid >> 2;      // channel 0..63
    const int g   = tid & 3;       // K-quarter group (lane bits 0-1)
    const int b0  = blockIdx.x * NB_;

    // ---- prologue: zero state buffers, stage x (re-strided to 16/timestep)
    for (int idx = tid; idx < NB_ * WP_; idx += THREADS_) h0[idx] = 0.f;
    for (int idx = tid; idx < NB_ * 16;  idx += THREADS_) snin[idx] = 0.f;
    for (int idx = tid; idx < NB_ * XPB_; idx += THREADS_) {
        int b = idx >> 10, r = idx & 1023, tt = r >> 4, i = r & 15;
        sx[idx] = (i < IN_) ? x[(size_t)(b0 + b) * (L_ * IN_) + tt * IN_ + i] : 0.f;
    }

    // ---- register-resident weight quarters (f32x2 pairs)
    ull wr2[8], wz2[8], wn2[8], wa2[8], wf2[8];
    {
        const ull* p;
        p = (const ull*)(Whh + (0 * H_ + j) * H_ + 16 * g);
        #pragma unroll
        for (int k = 0; k < 8; ++k) wr2[k] = p[k];
        p = (const ull*)(Whh + (1 * H_ + j) * H_ + 16 * g);
        #pragma unroll
        for (int k = 0; k < 8; ++k) wz2[k] = p[k];
        p = (const ull*)(Whh + (2 * H_ + j) * H_ + 16 * g);
        #pragma unroll
        for (int k = 0; k < 8; ++k) wn2[k] = p[k];
        p = (const ull*)(Wa + j * H_ + 16 * g);
        #pragma unroll
        for (int k = 0; k < 8; ++k) wa2[k] = p[k];
        p = (const ull*)(Wf + ((j < OUT_) ? j : 0) * H_ + 16 * g);
        #pragma unroll
        for (int k = 0; k < 8; ++k) wf2[k] = p[k];
    }
    float wir[4], wiz[4], win[4];
    #pragma unroll
    for (int i = 0; i < 4; ++i) {
        int c = 4 * g + i;
        bool v = (c < IN_);
        wir[i] = v ? Wih[(0 * H_ + j) * IN_ + c] : 0.f;
        wiz[i] = v ? Wih[(1 * H_ + j) * IN_ + c] : 0.f;
        win[i] = v ? Wih[(2 * H_ + j) * IN_ + c] : 0.f;
    }
    const float brr = bih[j]          + bhh[j];
    const float bzz = bih[H_ + j]     + bhh[H_ + j];
    const float bni = bih[2 * H_ + j];
    const float bnh = bhh[2 * H_ + j];
    const float bav = ba[j];
    const float bfv = (j < OUT_) ? bf[j] : 0.f;
    const int len0 = lengths[b0 + g];
    const int len1 = lengths[b0 + g + 4];

    __syncthreads();

    float h_own0 = 0.f, h_own1 = 0.f;

    // =======================  ENCODER  =======================
    for (int t = 0; t < L_; ++t) {
        const float* hrd = (t & 1) ? h1 : h0;
        float*       hwr = (t & 1) ? h0 : h1;

        float rs[8], zs[8], ns[8], is[8];
        #pragma unroll
        for (int b = 0; b < 8; ++b) {
            ull aR = 0, aZ = 0, aN = 0;
            #pragma unroll
            for (int k = 0; k < 4; ++k) {
                int kk = (k + g) & 3;   // stagger: conflict-free quarter reads
                ulonglong2 hq = *(const ulonglong2*)(hrd + b * WP_ + 16 * g + 4 * kk);
                aR = fma2_(wr2[2*kk], hq.x, aR); aR = fma2_(wr2[2*kk+1], hq.y, aR);
                aZ = fma2_(wz2[2*kk], hq.x, aZ); aZ = fma2_(wz2[2*kk+1], hq.y, aZ);
                aN = fma2_(wn2[2*kk], hq.x, aN); aN = fma2_(wn2[2*kk+1], hq.y, aN);
            }
            float4 xv = *(const float4*)(sx + b * XPB_ + t * XT_ + 4 * g);
            float iR = ((wir[0]*xv.x + wir[1]*xv.y) + (wir[2]*xv.z + wir[3]*xv.w));
            float iZ = ((wiz[0]*xv.x + wiz[1]*xv.y) + (wiz[2]*xv.z + wiz[3]*xv.w));
            float iN = ((win[0]*xv.x + win[1]*xv.y) + (win[2]*xv.z + win[3]*xv.w));
            rs[b] = hsum2_(aR) + iR;
            zs[b] = hsum2_(aZ) + iZ;
            ns[b] = hsum2_(aN);
            is[b] = iN;
        }
        reduce8_(rs, g); reduce8_(zs, g); reduce8_(ns, g); reduce8_(is, g);

        {   // owned batch g
            float r = sigmoid_(rs[g] + brr), z = sigmoid_(zs[g] + bzz);
            float n = tanh_(is[g] + bni + r * (ns[g] + bnh));
            float hn_ = (1.f - z) * n + z * h_own0;
            h_own0 = (t < len0) ? hn_ : h_own0;
            hwr[g * WP_ + j] = h_own0;
        }
        {   // owned batch g+4
            float r = sigmoid_(rs[g+4] + brr), z = sigmoid_(zs[g+4] + bzz);
            float n = tanh_(is[g+4] + bni + r * (ns[g+4] + bnh));
            float hn_ = (1.f - z) * n + z * h_own1;
            h_own1 = (t < len1) ? hn_ : h_own1;
            hwr[(g + 4) * WP_ + j] = h_own1;
        }
        __syncthreads();
    }

    // ---- nin = (len==L ? h_final : 0) @ Wf^T + bf
    so[g * WP_ + j]       = (len0 == L_) ? h_own0 : 0.f;
    so[(g + 4) * WP_ + j] = (len1 == L_) ? h_own1 : 0.f;
    __syncthreads();
    if (j < 16) {   // warps 0-1 (warp-uniform)
        float ya[8];
        #pragma unroll
        for (int b = 0; b < 8; ++b) {
            ull aY = 0;
            #pragma unroll
            for (int k = 0; k < 4; ++k) {
                int kk = (k + g) & 3;
                ulonglong2 oq = *(const ulonglong2*)(so + b * WP_ + 16 * g + 4 * kk);
                aY = fma2_(wf2[2*kk], oq.x, aY); aY = fma2_(wf2[2*kk+1], oq.y, aY);
            }
            ya[b] = hsum2_(aY);
        }
        reduce8_(ya, g);
        if (j < OUT_) {
            snin[g * 16 + j]       = ya[g]     + bfv;
            snin[(g + 4) * 16 + j] = ya[g + 4] + bfv;
        }
    }
    __syncthreads();

    // =======================  DECODER  =======================
    float m0 = -1e30f, s0 = 0.f, a0 = 0.f;
    float m1 = -1e30f, s1 = 0.f, a1 = 0.f;

    for (int t = 0; t < T_; ++t) {
        const float* hrd = (t & 1) ? h1 : h0;
        float*       hwr = (t & 1) ? h0 : h1;

        // ---- P1: gate pre-activations (quarter partials -> butterfly)
        float rs[8], zs[8], ns[8], is[8];
        #pragma unroll
        for (int b = 0; b < 8; ++b) {
            ull aR = 0, aZ = 0, aN = 0;
            #pragma unroll
            for (int k = 0; k < 4; ++k) {
                int kk = (k + g) & 3;
                ulonglong2 hq = *(const ulonglong2*)(hrd + b * WP_ + 16 * g + 4 * kk);
                aR = fma2_(wr2[2*kk], hq.x, aR); aR = fma2_(wr2[2*kk+1], hq.y, aR);
                aZ = fma2_(wz2[2*kk], hq.x, aZ); aZ = fma2_(wz2[2*kk+1], hq.y, aZ);
                aN = fma2_(wn2[2*kk], hq.x, aN); aN = fma2_(wn2[2*kk+1], hq.y, aN);
            }
            float4 nv = *(const float4*)(snin + b * 16 + 4 * g);
            float iR = ((wir[0]*nv.x + wir[1]*nv.y) + (wir[2]*nv.z + wir[3]*nv.w));
            float iZ = ((wiz[0]*nv.x + wiz[1]*nv.y) + (wiz[2]*nv.z + wiz[3]*nv.w));
            float iN = ((win[0]*nv.x + win[1]*nv.y) + (win[2]*nv.z + win[3]*nv.w));
            rs[b] = hsum2_(aR) + iR;
            zs[b] = hsum2_(aZ) + iZ;
            ns[b] = hsum2_(aN);
            is[b] = iN;
        }
        reduce8_(rs, g); reduce8_(zs, g); reduce8_(ns, g); reduce8_(is, g);

        float ov0, ov1;
        {
            float r = sigmoid_(rs[g] + brr), z = sigmoid_(zs[g] + bzz);
            float n = tanh_(is[g] + bni + r * (ns[g] + bnh));
            float hne = (1.f - z) * n + z * h_own0;
            float att = (t == 0) ? 0.f : __fdividef(a0, s0);
            ov0 = hne + att;
            h_own0 = hne;
            hwr[g * WP_ + j] = hne;
            so[g * WP_ + j]  = ov0;
        }
        {
            float r = sigmoid_(rs[g+4] + brr), z = sigmoid_(zs[g+4] + bzz);
            float n = tanh_(is[g+4] + bni + r * (ns[g+4] + bnh));
            float hne = (1.f - z) * n + z * h_own1;
            float att = (t == 0) ? 0.f : __fdividef(a1, s1);
            ov1 = hne + att;
            h_own1 = hne;
            hwr[(g + 4) * WP_ + j] = hne;
            so[(g + 4) * WP_ + j]  = ov1;
        }
        __syncthreads();   // S1: h/o published

        // ---- P3: logits (Wa) + outputs (Wf) from o
        float la[8], ya[8];
        #pragma unroll
        for (int b = 0; b < 8; ++b) {
            ull aA = 0, aY = 0;
            #pragma unroll
            for (int k = 0; k < 4; ++k) {
                int kk = (k + g) & 3;
                ulonglong2 oq = *(const ulonglong2*)(so + b * WP_ + 16 * g + 4 * kk);
                aA = fma2_(wa2[2*kk], oq.x, aA); aA = fma2_(wa2[2*kk+1], oq.y, aA);
                if (j < 16) {   // warp-uniform
                    aY = fma2_(wf2[2*kk], oq.x, aY); aY = fma2_(wf2[2*kk+1], oq.y, aY);
                }
            }
            la[b] = hsum2_(aA);
            ya[b] = (j < 16) ? hsum2_(aY) : 0.f;
        }
        reduce8_(la, g);
        if (j < 16) reduce8_(ya, g);

        {   // online softmax fold for owned batches (buf[t] = o)
            float l = la[g] + bav;
            float mn = fmaxf(m0, l);
            float c = __expf(m0 - mn), e = __expf(l - mn);
            s0 = s0 * c + e;  a0 = a0 * c + e * ov0;  m0 = mn;
        }
        {
            float l = la[g + 4] + bav;
            float mn = fmaxf(m1, l);
            float c = __expf(m1 - mn), e = __expf(l - mn);
            s1 = s1 * c + e;  a1 = a1 * c + e * ov1;  m1 = mn;
        }
        if (j < OUT_) {
            float y0 = ya[g]     + bfv;
            float y1 = ya[g + 4] + bfv;
            out[((size_t)(b0 + g)     * T_ + t) * OUT_ + j] = y0;
            out[((size_t)(b0 + g + 4) * T_ + t) * OUT_ + j] = y1;
            snin[g * 16 + j]       = y0;
            snin[(g + 4) * 16 + j] = y1;
        }
        __syncthreads();   // S2: snin (next decoder input) published
    }
}

extern "C" void kernel_launch(void* const* d_in, const int* in_sizes, int n_in,
                              void* d_out, int out_size) {
    const float* xp   = nullptr;
    const int*   lenp = nullptr;
    const float *Wihp = nullptr, *Whhp = nullptr, *bihp = nullptr, *bhhp = nullptr;
    const float *Wfp = nullptr, *bfp = nullptr, *Wap = nullptr, *bap = nullptr;

    for (int i = 0; i < n_in; ++i) {
        switch (in_sizes[i]) {
            case 1024 * 64 * 13: xp   = (const float*)d_in[i]; break;
            case 1024:           lenp = (const int*)d_in[i];   break;
            case 192 * 13:       Wihp = (const float*)d_in[i]; break;
            case 192 * 64:       Whhp = (const float*)d_in[i]; break;
            case 192:
                if (!bihp) bihp = (const float*)d_in[i];
                else       bhhp = (const float*)d_in[i];
                break;
            case 13 * 64:        Wfp  = (const float*)d_in[i]; break;
            case 13:             bfp  = (const float*)d_in[i]; break;
            case 64 * 64:        Wap  = (const float*)d_in[i]; break;
            case 64:             bap  = (const float*)d_in[i]; break;
            default: break;   // output_length scalar -> T=128 hardcoded
        }
    }

    gru_attn_kernel<<<BLOCKS_, THREADS_>>>(
        xp, lenp, Wihp, Whhp, bihp, bhhp, Wfp, bfp, Wap, bap, (float*)d_out);
}

// round 11
// speedup vs baseline: 1.4516x; 1.4516x over previous
#include <cuda_runtime.h>

// ---------------------------------------------------------------------------
// AutoregressiveGRUWithAttention  (B=1024, L=64, T=128, IN=13, H=64, OUT=13)
//
// R10 = R9 structure with register pressure fixed.
//  128 blocks x 256 threads; j = tid>>2 (channel), g = tid&3 (K-quarter, in
//  lane bits). Whh/Wa/Wf quarter-rows register-resident as f32x2 pairs ->
//  zero weight smem traffic. Batches processed in two HALVES of 4 so partial
//  arrays are 4-wide (16 regs, not 32). Butterfly reduction is unmasked
//  (xor1 + xor2 -> full sum in every lane), thread g owns batch 4*half+g.
//  h double-buffered; 1 sync/encoder step, 2 syncs/decoder step.
//  Online-softmax attention (validated R7-R9, rel_err ~4e-7).
// ---------------------------------------------------------------------------

typedef unsigned long long ull;

namespace {
constexpr int L_   = 64;
constexpr int T_   = 128;
constexpr int IN_  = 13;
constexpr int H_   = 64;
constexpr int OUT_ = 13;
constexpr int NB_  = 8;
constexpr int THREADS_ = 256;
constexpr int BLOCKS_  = 128;
constexpr int WP_  = 72;             // h/o row stride
constexpr int XT_  = 16;             // padded x stride per timestep
constexpr int XPB_ = L_ * XT_;       // 1024 floats per batch

constexpr int SM_H0  = 0;                    // [8][72] ping
constexpr int SM_H1  = SM_H0 + NB_ * WP_;    // [8][72] pong
constexpr int SM_O   = SM_H1 + NB_ * WP_;    // [8][72]
constexpr int SM_NIN = SM_O  + NB_ * WP_;    // [8][16]
constexpr int SM_X   = SM_NIN + NB_ * 16;    // [8][1024]
constexpr int SM_FLOATS = SM_X + NB_ * XPB_; // 10048 floats = 40.2 KB
}

__device__ __forceinline__ ull fma2_(ull a, ull b, ull c) {
    ull d;
    asm("fma.rn.f32x2 %0, %1, %2, %3;" : "=l"(d) : "l"(a), "l"(b), "l"(c));
    return d;
}
__device__ __forceinline__ float hsum2_(ull a) {
    unsigned lo, hi;
    asm("mov.b64 {%0, %1}, %2;" : "=r"(lo), "=r"(hi) : "l"(a));
    return __uint_as_float(lo) + __uint_as_float(hi);
}
__device__ __forceinline__ float sigmoid_(float a) {
    return __fdividef(1.f, 1.f + __expf(-a));
}
__device__ __forceinline__ float tanh_(float a) {
    float c  = fminf(fmaxf(a, -15.f), 15.f);
    float e2 = __expf(2.f * c);
    return __fdividef(e2 - 1.f, e2 + 1.f);
}
// Full sum of each element across the 4-lane quarter cluster (lanes 4q..4q+3).
__device__ __forceinline__ void reduce4_(float (&A)[4]) {
    #pragma unroll
    for (int b = 0; b < 4; ++b) {
        A[b] += __shfl_xor_sync(0xFFFFFFFFu, A[b], 1);
        A[b] += __shfl_xor_sync(0xFFFFFFFFu, A[b], 2);
    }
}

__global__ void __launch_bounds__(THREADS_, 1)
gru_attn_kernel(const float* __restrict__ x, const int* __restrict__ lengths,
                const float* __restrict__ Wih, const float* __restrict__ Whh,
                const float* __restrict__ bih, const float* __restrict__ bhh,
                const float* __restrict__ Wf,  const float* __restrict__ bf,
                const float* __restrict__ Wa,  const float* __restrict__ ba,
                float* __restrict__ out)
{
    __shared__ __align__(16) float sm[SM_FLOATS];
    __shared__ int smax;
    float* h0   = sm + SM_H0;
    float* h1   = sm + SM_H1;
    float* so   = sm + SM_O;
    float* snin = sm + SM_NIN;
    float* sx   = sm + SM_X;

    const int tid = threadIdx.x;
    const int j   = tid >> 2;      // channel 0..63
    const int g   = tid & 3;       // K-quarter (lane bits 0-1)
    const int b0  = blockIdx.x * NB_;

    // ---- prologue
    for (int idx = tid; idx < NB_ * WP_; idx += THREADS_) h0[idx] = 0.f;
    for (int idx = tid; idx < NB_ * 16;  idx += THREADS_) snin[idx] = 0.f;
    for (int idx = tid; idx < NB_ * XPB_; idx += THREADS_) {
        int b = idx >> 10, r = idx & 1023, tt = r >> 4, i = r & 15;
        sx[idx] = (i < IN_) ? x[(size_t)(b0 + b) * (L_ * IN_) + tt * IN_ + i] : 0.f;
    }
    if (tid == 0) {
        int m = 0;
        #pragma unroll
        for (int b = 0; b < NB_; ++b) m = max(m, lengths[b0 + b]);
        smax = m;
    }

    // ---- register-resident weight quarters (f32x2 pairs)
    ull wr2[8], wz2[8], wn2[8], wa2[8], wf2[8];
    {
        const ull* p;
        p = (const ull*)(Whh + (0 * H_ + j) * H_ + 16 * g);
        #pragma unroll
        for (int k = 0; k < 8; ++k) wr2[k] = p[k];
        p = (const ull*)(Whh + (1 * H_ + j) * H_ + 16 * g);
        #pragma unroll
        for (int k = 0; k < 8; ++k) wz2[k] = p[k];
        p = (const ull*)(Whh + (2 * H_ + j) * H_ + 16 * g);
        #pragma unroll
        for (int k = 0; k < 8; ++k) wn2[k] = p[k];
        p = (const ull*)(Wa + j * H_ + 16 * g);
        #pragma unroll
        for (int k = 0; k < 8; ++k) wa2[k] = p[k];
        p = (const ull*)(Wf + ((j < OUT_) ? j : 0) * H_ + 16 * g);
        #pragma unroll
        for (int k = 0; k < 8; ++k) wf2[k] = p[k];
    }
    float wir[4], wiz[4], win[4];
    #pragma unroll
    for (int i = 0; i < 4; ++i) {
        int c = 4 * g + i;
        bool v = (c < IN_);
        wir[i] = v ? Wih[(0 * H_ + j) * IN_ + c] : 0.f;
        wiz[i] = v ? Wih[(1 * H_ + j) * IN_ + c] : 0.f;
        win[i] = v ? Wih[(2 * H_ + j) * IN_ + c] : 0.f;
    }
    const float brr = bih[j]          + bhh[j];
    const float bzz = bih[H_ + j]     + bhh[H_ + j];
    const float bni = bih[2 * H_ + j];
    const float bnh = bhh[2 * H_ + j];
    const float bav = ba[j];
    const float bfv = (j < OUT_) ? bf[j] : 0.f;
    const int len0 = lengths[b0 + g];        // owned batch g
    const int len1 = lengths[b0 + 4 + g];    // owned batch g+4

    __syncthreads();
    const int Lmax = smax;

    float h_own0 = 0.f, h_own1 = 0.f;

    // =======================  ENCODER  =======================
    for (int t = 0; t < Lmax; ++t) {
        const float* hrd = (t & 1) ? h1 : h0;
        float*       hwr = (t & 1) ? h0 : h1;

        #pragma unroll
        for (int hh = 0; hh < 2; ++hh) {
            float pr[4], pz[4], pn[4], pi[4];
            #pragma unroll
            for (int bi = 0; bi < 4; ++bi) {
                const int b = 4 * hh + bi;
                ull aR = 0, aZ = 0, aN = 0;
                #pragma unroll
                for (int k = 0; k < 4; ++k) {
                    int kk = (k + g) & 3;   // staggered: conflict-free
                    ulonglong2 hq = *(const ulonglong2*)(hrd + b * WP_ + 16 * g + 4 * kk);
                    aR = fma2_(wr2[2*kk], hq.x, aR); aR = fma2_(wr2[2*kk+1], hq.y, aR);
                    aZ = fma2_(wz2[2*kk], hq.x, aZ); aZ = fma2_(wz2[2*kk+1], hq.y, aZ);
                    aN = fma2_(wn2[2*kk], hq.x, aN); aN = fma2_(wn2[2*kk+1], hq.y, aN);
                }
                float4 xv = *(const float4*)(sx + b * XPB_ + t * XT_ + 4 * g);
                pr[bi] = hsum2_(aR) + ((wir[0]*xv.x + wir[1]*xv.y) + (wir[2]*xv.z + wir[3]*xv.w));
                pz[bi] = hsum2_(aZ) + ((wiz[0]*xv.x + wiz[1]*xv.y) + (wiz[2]*xv.z + wiz[3]*xv.w));
                pn[bi] = hsum2_(aN);
                pi[bi] = ((win[0]*xv.x + win[1]*xv.y) + (win[2]*xv.z + win[3]*xv.w));
            }
            reduce4_(pr); reduce4_(pz); reduce4_(pn); reduce4_(pi);

            // owned batch: 4*hh + g
            float r = sigmoid_(pr[g] + brr), z = sigmoid_(pz[g] + bzz);
            float n = tanh_(pi[g] + bni + r * (pn[g] + bnh));
            if (hh == 0) {
                float hn_ = (1.f - z) * n + z * h_own0;
                h_own0 = (t < len0) ? hn_ : h_own0;
                hwr[g * WP_ + j] = h_own0;
            } else {
                float hn_ = (1.f - z) * n + z * h_own1;
                h_own1 = (t < len1) ? hn_ : h_own1;
                hwr[(4 + g) * WP_ + j] = h_own1;
            }
        }
        __syncthreads();
    }

    // ---- nin = (len==L ? h_final : 0) @ Wf^T + bf; also reset h parity to h0
    h0[g * WP_ + j]       = h_own0;
    h0[(4 + g) * WP_ + j] = h_own1;
    so[g * WP_ + j]       = (len0 == L_) ? h_own0 : 0.f;
    so[(4 + g) * WP_ + j] = (len1 == L_) ? h_own1 : 0.f;
    __syncthreads();
    if (j < 16) {   // warps 0-1 (warp-uniform predicate)
        #pragma unroll
        for (int hh = 0; hh < 2; ++hh) {
            float ya[4];
            #pragma unroll
            for (int bi = 0; bi < 4; ++bi) {
                const int b = 4 * hh + bi;
                ull aY = 0;
                #pragma unroll
                for (int k = 0; k < 4; ++k) {
                    int kk = (k + g) & 3;
                    ulonglong2 oq = *(const ulonglong2*)(so + b * WP_ + 16 * g + 4 * kk);
                    aY = fma2_(wf2[2*kk], oq.x, aY); aY = fma2_(wf2[2*kk+1], oq.y, aY);
                }
                ya[bi] = hsum2_(aY);
            }
            reduce4_(ya);
            if (j < OUT_) snin[(4 * hh + g) * 16 + j] = ya[g] + bfv;
        }
    }
    __syncthreads();

    // =======================  DECODER  =======================
    float m0 = -1e30f, s0 = 0.f, a0 = 0.f;
    float m1 = -1e30f, s1 = 0.f, a1 = 0.f;

    for (int t = 0; t < T_; ++t) {
        const float* hrd = (t & 1) ? h1 : h0;
        float*       hwr = (t & 1) ? h0 : h1;

        float ov0, ov1;
        // ---- P1: gates for both halves
        #pragma unroll
        for (int hh = 0; hh < 2; ++hh) {
            float pr[4], pz[4], pn[4], pi[4];
            #pragma unroll
            for (int bi = 0; bi < 4; ++bi) {
                const int b = 4 * hh + bi;
                ull aR = 0, aZ = 0, aN = 0;
                #pragma unroll
                for (int k = 0; k < 4; ++k) {
                    int kk = (k + g) & 3;
                    ulonglong2 hq = *(const ulonglong2*)(hrd + b * WP_ + 16 * g + 4 * kk);
                    aR = fma2_(wr2[2*kk], hq.x, aR); aR = fma2_(wr2[2*kk+1], hq.y, aR);
                    aZ = fma2_(wz2[2*kk], hq.x, aZ); aZ = fma2_(wz2[2*kk+1], hq.y, aZ);
                    aN = fma2_(wn2[2*kk], hq.x, aN); aN = fma2_(wn2[2*kk+1], hq.y, aN);
                }
                float4 nv = *(const float4*)(snin + b * 16 + 4 * g);
                pr[bi] = hsum2_(aR) + ((wir[0]*nv.x + wir[1]*nv.y) + (wir[2]*nv.z + wir[3]*nv.w));
                pz[bi] = hsum2_(aZ) + ((wiz[0]*nv.x + wiz[1]*nv.y) + (wiz[2]*nv.z + wiz[3]*nv.w));
                pn[bi] = hsum2_(aN);
                pi[bi] = ((win[0]*nv.x + win[1]*nv.y) + (win[2]*nv.z + win[3]*nv.w));
            }
            reduce4_(pr); reduce4_(pz); reduce4_(pn); reduce4_(pi);

            float r = sigmoid_(pr[g] + brr), z = sigmoid_(pz[g] + bzz);
            float n = tanh_(pi[g] + bni + r * (pn[g] + bnh));
            if (hh == 0) {
                float hne = (1.f - z) * n + z * h_own0;
                float att = (t == 0) ? 0.f : __fdividef(a0, s0);
                ov0 = hne + att;
                h_own0 = hne;
                hwr[g * WP_ + j] = hne;
                so[g * WP_ + j]  = ov0;
            } else {
                float hne = (1.f - z) * n + z * h_own1;
                float att = (t == 0) ? 0.f : __fdividef(a1, s1);
                ov1 = hne + att;
                h_own1 = hne;
                hwr[(4 + g) * WP_ + j] = hne;
                so[(4 + g) * WP_ + j]  = ov1;
            }
        }
        __syncthreads();   // S1: new h / o published

        // ---- P3: logits (Wa) + outputs (Wf) from o
        #pragma unroll
        for (int hh = 0; hh < 2; ++hh) {
            float la[4], ya[4];
            #pragma unroll
            for (int bi = 0; bi < 4; ++bi) {
                const int b = 4 * hh + bi;
                ull aA = 0, aY = 0;
                #pragma unroll
                for (int k = 0; k < 4; ++k) {
                    int kk = (k + g) & 3;
                    ulonglong2 oq = *(const ulonglong2*)(so + b * WP_ + 16 * g + 4 * kk);
                    aA = fma2_(wa2[2*kk], oq.x, aA); aA = fma2_(wa2[2*kk+1], oq.y, aA);
                    if (j < 16) {   // warps 0-1 only
                        aY = fma2_(wf2[2*kk], oq.x, aY); aY = fma2_(wf2[2*kk+1], oq.y, aY);
                    }
                }
                la[bi] = hsum2_(aA);
                ya[bi] = (j < 16) ? hsum2_(aY) : 0.f;
            }
            reduce4_(la);
            if (j < 16) reduce4_(ya);

            // online softmax fold for owned batch (buf[t] = o)
            float l = la[g] + bav;
            if (hh == 0) {
                float mn = fmaxf(m0, l);
                float c = __expf(m0 - mn), e = __expf(l - mn);
                s0 = s0 * c + e;  a0 = a0 * c + e * ov0;  m0 = mn;
            } else {
                float mn = fmaxf(m1, l);
                float c = __expf(m1 - mn), e = __expf(l - mn);
                s1 = s1 * c + e;  a1 = a1 * c + e * ov1;  m1 = mn;
            }
            if (j < OUT_) {
                float y = ya[g] + bfv;
                const int b = 4 * hh + g;
                out[((size_t)(b0 + b) * T_ + t) * OUT_ + j] = y;
                snin[b * 16 + j] = y;
            }
        }
        __syncthreads();   // S2: snin (next decoder input) published
    }
}

extern "C" void kernel_launch(void* const* d_in, const int* in_sizes, int n_in,
                              void* d_out, int out_size) {
    const float* xp   = nullptr;
    const int*   lenp = nullptr;
    const float *Wihp = nullptr, *Whhp = nullptr, *bihp = nullptr, *bhhp = nullptr;
    const float *Wfp = nullptr, *bfp = nullptr, *Wap = nullptr, *bap = nullptr;

    for (int i = 0; i < n_in; ++i) {
        switch (in_sizes[i]) {
            case 1024 * 64 * 13: xp   = (const float*)d_in[i]; break;
            case 1024:           lenp = (const int*)d_in[i];   break;
            case 192 * 13:       Wihp = (const float*)d_in[i]; break;
            case 192 * 64:       Whhp = (const float*)d_in[i]; break;
            case 192:
                if (!bihp) bihp = (const float*)d_in[i];
                else       bhhp = (const float*)d_in[i];
                break;
            case 13 * 64:        Wfp  = (const float*)d_in[i]; break;
            case 13:             bfp  = (const float*)d_in[i]; break;
            case 64 * 64:        Wap  = (const float*)d_in[i]; break;
            case 64:             bap  = (const float*)d_in[i]; break;
            default: break;   // output_length scalar -> T=128 hardcoded
        }
    }

    gru_attn_kernel<<<BLOCKS_, THREADS_>>>(
        xp, lenp, Wihp, Whhp, bihp, bhhp, Wfp, bfp, Wap, bap, (float*)d_out);
}

// round 12
// speedup vs baseline: 1.7732x; 1.2216x over previous
#include <cuda_runtime.h>

// ---------------------------------------------------------------------------
// AutoregressiveGRUWithAttention  (B=1024, L=64, T=128, IN=13, H=64, OUT=13)
//
// R11: phase-parallel persistent kernel. 128 blocks x 256 threads (8 warps),
// 8 batches/block.
//   P1: warps 0-5 -> one (gate, channel) Whh row per thread, REGISTER-resident
//       (64 regs), Whh.h for all 8 batches via smem h broadcasts.
//       warps 6-7 -> Wih.(nin|x_t) small dots (weights from smem).
//   P2: thread (b-pair, j) owns h / online-softmax state in registers;
//       elementwise GRU update + attention add.
//   P3: Wa(64)+Wf(13) rows x 2 K-halves on warps 0-4; halves combined with
//       shfl_xor(1); rotated-chunk o reads avoid bank conflicts.
//   P4: fold new logit into per-(b,j) online softmax (== reference's masked
//       full-buffer softmax; validated rel_err ~4e-7 in R7-R10).
// ---------------------------------------------------------------------------

typedef unsigned long long ull;

namespace {
constexpr int L_ = 64, T_ = 128, IN_ = 13, H_ = 64, OUT_ = 13, NB_ = 8;
constexpr int THREADS_ = 256, BLOCKS_ = 128;
constexpr int HS_   = 68;            // state row stride (floats)
constexpr int GP_   = NB_ * HS_;     // 544: one gate plane [8][68]
constexpr int WIHS_ = 20;            // Wih smem row stride (16B aligned, pad 0)
constexpr int W3S_  = 68;            // Wa|Wf smem row stride
constexpr int XT_   = 16, XPB_ = L_ * XT_;   // x staging: 16/step, 1024/batch

constexpr int SM_SH  = 0;                    // h      [8][68]
constexpr int SM_SO  = SM_SH  + GP_;         // o      [8][68]
constexpr int SM_GH  = SM_SO  + GP_;         // Whh.h  [3][8][68]
constexpr int SM_GI  = SM_GH  + 3 * GP_;     // Wih.in [3][8][68]
constexpr int SM_LG  = SM_GI  + 3 * GP_;     // logits [8][68]
constexpr int SM_NIN = SM_LG  + GP_;         // y_prev [8][16]
constexpr int SM_W3  = SM_NIN + NB_ * 16;    // [77][68] = Wa rows 0-63, Wf 64-76
constexpr int SM_WIH = SM_W3  + 77 * W3S_;   // [192][20]
constexpr int SM_SX  = SM_WIH + 192 * WIHS_; // [8][1024]
constexpr int SM_FLOATS = SM_SX + NB_ * XPB_;
constexpr int SMEM_BYTES = SM_FLOATS * 4;    // ~89.2 KB (dynamic)
}

__device__ __forceinline__ ull fma2_(ull a, ull b, ull c) {
    ull d;
    asm("fma.rn.f32x2 %0, %1, %2, %3;" : "=l"(d) : "l"(a), "l"(b), "l"(c));
    return d;
}
__device__ __forceinline__ float hsum2_(ull a) {
    unsigned lo, hi;
    asm("mov.b64 {%0, %1}, %2;" : "=r"(lo), "=r"(hi) : "l"(a));
    return __uint_as_float(lo) + __uint_as_float(hi);
}
__device__ __forceinline__ float sigmoid_(float a) {
    return __fdividef(1.f, 1.f + __expf(-a));
}
__device__ __forceinline__ float tanh_(float a) {
    float c  = fminf(fmaxf(a, -15.f), 15.f);
    float e2 = __expf(2.f * c);
    return __fdividef(e2 - 1.f, e2 + 1.f);
}
__device__ __forceinline__ float dot4_(float4 a, float4 b) {
    return (a.x * b.x + a.y * b.y) + (a.z * b.z + a.w * b.w);
}

// P1 row thread: gh[gate][b][jrow] = Whh_row . h[b]  (weights in registers)
__device__ __forceinline__ void p1_rows(const ull (&w2)[32], const float* sh,
                                        float* ghg, int jrow) {
    #pragma unroll
    for (int b2 = 0; b2 < 4; ++b2) {
        const float* ha = sh + (2 * b2)     * HS_;
        const float* hb = sh + (2 * b2 + 1) * HS_;
        ull aa = 0, ab = 0;
        #pragma unroll
        for (int c = 0; c < 16; ++c) {
            ulonglong2 a4 = *(const ulonglong2*)(ha + 4 * c);
            ulonglong2 b4 = *(const ulonglong2*)(hb + 4 * c);
            aa = fma2_(w2[2*c], a4.x, aa); aa = fma2_(w2[2*c+1], a4.y, aa);
            ab = fma2_(w2[2*c], b4.x, ab); ab = fma2_(w2[2*c+1], b4.y, ab);
        }
        ghg[(2 * b2)     * HS_ + jrow] = hsum2_(aa);
        ghg[(2 * b2 + 1) * HS_ + jrow] = hsum2_(ab);
    }
}

// P1 gi thread: gi[g][b][jgi] = Wih_row(g,jgi) . src[b]   (13-wide dots)
__device__ __forceinline__ void p1_gi(const float* sWih, float* gi, int jgi,
                                      const float* src, int stride) {
    float4 wr4[4], wz4[4], wn4[4];
    #pragma unroll
    for (int c = 0; c < 4; ++c) {
        wr4[c] = *(const float4*)(sWih + jgi         * WIHS_ + 4 * c);
        wz4[c] = *(const float4*)(sWih + (64  + jgi) * WIHS_ + 4 * c);
        wn4[c] = *(const float4*)(sWih + (128 + jgi) * WIHS_ + 4 * c);
    }
    #pragma unroll
    for (int b = 0; b < 8; ++b) {
        const float4* v = (const float4*)(src + b * stride);
        float4 v0 = v[0], v1 = v[1], v2 = v[2], v3 = v[3];
        float ar = (dot4_(wr4[0], v0) + dot4_(wr4[1], v1)) +
                   (dot4_(wr4[2], v2) + dot4_(wr4[3], v3));
        float az = (dot4_(wz4[0], v0) + dot4_(wz4[1], v1)) +
                   (dot4_(wz4[2], v2) + dot4_(wz4[3], v3));
        float an = (dot4_(wn4[0], v0) + dot4_(wn4[1], v1)) +
                   (dot4_(wn4[2], v2) + dot4_(wn4[3], v3));
        gi[0 * GP_ + b * HS_ + jgi] = ar;
        gi[1 * GP_ + b * HS_ + jgi] = az;
        gi[2 * GP_ + b * HS_ + jgi] = an;
    }
}

// P3: rows 0-63 -> logits (Wa), rows 64-76 -> y (Wf) into snin (+out).
// Each row split in 2 K-halves on adjacent lanes; shfl_xor(1) combines.
// half==1 lanes walk chunks rotated by 1 so the two per-instruction smem
// addresses never share banks (diff = 144B or 80B).
__device__ __forceinline__ void p3_all(const float* sW3, const float* so,
                                       float* slg, float* snin,
                                       float* __restrict__ out_g, float bfr,
                                       int row, int half, int b0, int t,
                                       bool write_out) {
    const bool valid = (row < 77);
    const float* wbase = sW3 + row * W3S_ + half * 32;
    float part[8] = {0.f, 0.f, 0.f, 0.f, 0.f, 0.f, 0.f, 0.f};
    #pragma unroll
    for (int pass = 0; pass < 2; ++pass) {
        ulonglong2 wv[4];
        int cis[4];
        #pragma unroll
        for (int i = 0; i < 4; ++i) {
            cis[i] = 4 * pass + ((i + half) & 3);
            if (valid) wv[i] = *(const ulonglong2*)(wbase + 4 * cis[i]);
            else       { wv[i].x = 0; wv[i].y = 0; }
        }
        #pragma unroll
        for (int b = 0; b < 8; ++b) {
            const float* ob = so + b * HS_ + half * 32;
            ull acc = 0;
            #pragma unroll
            for (int i = 0; i < 4; ++i) {
                ulonglong2 o2 = *(const ulonglong2*)(ob + 4 * cis[i]);
                acc = fma2_(wv[i].x, o2.x, acc);
                acc = fma2_(wv[i].y, o2.y, acc);
            }
            part[b] += hsum2_(acc);
        }
    }
    #pragma unroll
    for (int b = 0; b < 8; ++b)
        part[b] += __shfl_xor_sync(0xFFFFFFFFu, part[b], 1);
    if (half == 0 && valid) {
        if (row < 64) {
            #pragma unroll
            for (int b = 0; b < 8; ++b) slg[b * HS_ + row] = part[b];
        } else {
            const int oc = row - 64;
            #pragma unroll
            for (int b = 0; b < 8; ++b) {
                float y = part[b] + bfr;
                snin[b * 16 + oc] = y;
                if (write_out)
                    out_g[((size_t)(b0 + b) * T_ + t) * OUT_ + oc] = y;
            }
        }
    }
}

__global__ void __launch_bounds__(THREADS_, 1)
gru_attn_kernel(const float* __restrict__ x, const int* __restrict__ lengths,
                const float* __restrict__ Wih, const float* __restrict__ Whh,
                const float* __restrict__ bih, const float* __restrict__ bhh,
                const float* __restrict__ Wf,  const float* __restrict__ bf,
                const float* __restrict__ Wa,  const float* __restrict__ ba,
                float* __restrict__ out)
{
    extern __shared__ float sm[];
    float* sh   = sm + SM_SH;
    float* so   = sm + SM_SO;
    float* gh   = sm + SM_GH;
    float* gi   = sm + SM_GI;
    float* slg  = sm + SM_LG;
    float* snin = sm + SM_NIN;
    float* sW3  = sm + SM_W3;
    float* sWih = sm + SM_WIH;
    float* sx   = sm + SM_SX;
    __shared__ int smax;

    const int tid  = threadIdx.x;
    const int w    = tid >> 5;
    const int lane = tid & 31;
    const int b0   = blockIdx.x * NB_;

    // role indices
    const int gate = w >> 1;                    // warps 0-5
    const int jrow = (w & 1) * 32 + lane;
    const int jgi  = (w - 6) * 32 + lane;       // warps 6-7
    const int row3 = 16 * w + (lane >> 1);      // warps 0-4 (P3)
    const int half3 = lane & 1;
    // P2/P4 ownership
    const int j2 = tid & 63;
    const int bp = tid >> 6;                    // owns batches bp, bp+4

    // ---- prologue: stage Wa|Wf, Wih (zero-padded), x; zero state buffers
    for (int idx = tid; idx < 77 * H_; idx += THREADS_) {
        int r = idx >> 6, c = idx & 63;
        sW3[r * W3S_ + c] = (r < 64) ? Wa[r * H_ + c] : Wf[(r - 64) * H_ + c];
    }
    for (int idx = tid; idx < 192 * WIHS_; idx += THREADS_) {
        int r = idx / WIHS_, c = idx - r * WIHS_;
        sWih[idx] = (c < IN_) ? Wih[r * IN_ + c] : 0.f;
    }
    for (int idx = tid; idx < NB_ * XPB_; idx += THREADS_) {
        int b = idx >> 10, r = idx & 1023, tt = r >> 4, i = r & 15;
        sx[idx] = (i < IN_) ? x[(size_t)(b0 + b) * (L_ * IN_) + tt * IN_ + i] : 0.f;
    }
    for (int idx = tid; idx < GP_; idx += THREADS_) sh[idx] = 0.f;
    for (int idx = tid; idx < NB_ * 16; idx += THREADS_) snin[idx] = 0.f;
    if (tid == 0) {
        int m = 0;
        #pragma unroll
        for (int b = 0; b < NB_; ++b) m = max(m, lengths[b0 + b]);
        smax = m;
    }

    // register-resident Whh row for warps 0-5
    ull whh2[32];
    if (w < 6) {
        const ull* p = (const ull*)(Whh + (gate * H_ + jrow) * H_);
        #pragma unroll
        for (int k = 0; k < 32; ++k) whh2[k] = p[k];
    }

    // per-thread biases / lengths (P2/P4 map)
    const float brr = bih[j2] + bhh[j2];
    const float bzz = bih[H_ + j2] + bhh[H_ + j2];
    const float bni = bih[2 * H_ + j2];
    const float bnh = bhh[2 * H_ + j2];
    const float bav = ba[j2];
    const int len0 = lengths[b0 + bp];
    const int len1 = lengths[b0 + bp + 4];
    float bfr = 0.f;
    if (w == 4 && row3 >= 64 && row3 < 77) bfr = bf[row3 - 64];

    __syncthreads();
    const int Lmax = smax;

    float h_own0 = 0.f, h_own1 = 0.f;

    // =======================  ENCODER  =======================
    for (int t = 0; t < Lmax; ++t) {
        if (w < 6) p1_rows(whh2, sh, gh + gate * GP_, jrow);
        else       p1_gi(sWih, gi, jgi, sx + t * XT_, XPB_);
        __syncthreads();   // S1: gh/gi ready

        {   // owned batch bp
            const int o_ = bp * HS_ + j2;
            float r = sigmoid_(gh[o_] + gi[o_] + brr);
            float z = sigmoid_(gh[GP_ + o_] + gi[GP_ + o_] + bzz);
            float n = tanh_((gi[2 * GP_ + o_] + bni) + r * (gh[2 * GP_ + o_] + bnh));
            float hne = (1.f - z) * n + z * h_own0;
            h_own0 = (t < len0) ? hne : h_own0;
            sh[o_] = h_own0;
        }
        {   // owned batch bp+4
            const int o_ = (bp + 4) * HS_ + j2;
            float r = sigmoid_(gh[o_] + gi[o_] + brr);
            float z = sigmoid_(gh[GP_ + o_] + gi[GP_ + o_] + bzz);
            float n = tanh_((gi[2 * GP_ + o_] + bni) + r * (gh[2 * GP_ + o_] + bnh));
            float hne = (1.f - z) * n + z * h_own1;
            h_own1 = (t < len1) ? hne : h_own1;
            sh[o_] = h_own1;
        }
        __syncthreads();   // S2: h ready
    }

    // ---- nin = (len==L ? h : 0) @ Wf^T + bf  (via P3 machinery, Wf rows)
    so[bp * HS_ + j2]       = (len0 == L_) ? h_own0 : 0.f;
    so[(bp + 4) * HS_ + j2] = (len1 == L_) ? h_own1 : 0.f;
    __syncthreads();
    if (w < 5) p3_all(sW3, so, slg, snin, out, bfr, row3, half3, b0, 0, false);
    __syncthreads();

    // =======================  DECODER  =======================
    float m0 = -1e30f, s0 = 0.f, a0 = 0.f;
    float m1 = -1e30f, s1 = 0.f, a1 = 0.f;

    for (int t = 0; t < T_; ++t) {
        // P1
        if (w < 6) p1_rows(whh2, sh, gh + gate * GP_, jrow);
        else       p1_gi(sWih, gi, jgi, snin, 16);
        __syncthreads();   // S1

        // P2: GRU update + attention add, publish h and o
        float ov0, ov1;
        {
            const int o_ = bp * HS_ + j2;
            float r = sigmoid_(gh[o_] + gi[o_] + brr);
            float z = sigmoid_(gh[GP_ + o_] + gi[GP_ + o_] + bzz);
            float n = tanh_((gi[2 * GP_ + o_] + bni) + r * (gh[2 * GP_ + o_] + bnh));
            float hne = (1.f - z) * n + z * h_own0;
            float att = (t == 0) ? 0.f : __fdividef(a0, s0);
            ov0 = hne + att;
            h_own0 = hne;
            sh[o_] = hne;
            so[o_] = ov0;
        }
        {
            const int o_ = (bp + 4) * HS_ + j2;
            float r = sigmoid_(gh[o_] + gi[o_] + brr);
            float z = sigmoid_(gh[GP_ + o_] + gi[GP_ + o_] + bzz);
            float n = tanh_((gi[2 * GP_ + o_] + bni) + r * (gh[2 * GP_ + o_] + bnh));
            float hne = (1.f - z) * n + z * h_own1;
            float att = (t == 0) ? 0.f : __fdividef(a1, s1);
            ov1 = hne + att;
            h_own1 = hne;
            sh[o_] = hne;
            so[o_] = ov1;
        }
        __syncthreads();   // S2: h/o ready

        // P3: logits + y
        if (w < 5) p3_all(sW3, so, slg, snin, out, bfr, row3, half3, b0, t, true);
        __syncthreads();   // S3: logits/snin ready

        // P4: fold new (logit, o) into online softmax (buf[t] = o)
        {
            float l = slg[bp * HS_ + j2] + bav;
            float mn = fmaxf(m0, l);
            float c = __expf(m0 - mn), e = __expf(l - mn);
            s0 = s0 * c + e;  a0 = a0 * c + e * ov0;  m0 = mn;
        }
        {
            float l = slg[(bp + 4) * HS_ + j2] + bav;
            float mn = fmaxf(m1, l);
            float c = __expf(m1 - mn), e = __expf(l - mn);
            s1 = s1 * c + e;  a1 = a1 * c + e * ov1;  m1 = mn;
        }
        // no sync needed: next P1 reads sh (pre-S3) and snin (pre-S3);
        // slg is only rewritten after the next S2.
    }
}

extern "C" void kernel_launch(void* const* d_in, const int* in_sizes, int n_in,
                              void* d_out, int out_size) {
    const float* xp   = nullptr;
    const int*   lenp = nullptr;
    const float *Wihp = nullptr, *Whhp = nullptr, *bihp = nullptr, *bhhp = nullptr;
    const float *Wfp = nullptr, *bfp = nullptr, *Wap = nullptr, *bap = nullptr;

    for (int i = 0; i < n_in; ++i) {
        switch (in_sizes[i]) {
            case 1024 * 64 * 13: xp   = (const float*)d_in[i]; break;
            case 1024:           lenp = (const int*)d_in[i];   break;
            case 192 * 13:       Wihp = (const float*)d_in[i]; break;
            case 192 * 64:       Whhp = (const float*)d_in[i]; break;
            case 192:
                if (!bihp) bihp = (const float*)d_in[i];
                else       bhhp = (const float*)d_in[i];
                break;
            case 13 * 64:        Wfp  = (const float*)d_in[i]; break;
            case 13:             bfp  = (const float*)d_in[i]; break;
            case 64 * 64:        Wap  = (const float*)d_in[i]; break;
            case 64:             bap  = (const float*)d_in[i]; break;
            default: break;   // output_length scalar -> T=128 hardcoded
        }
    }

    cudaFuncSetAttribute(gru_attn_kernel,
                         cudaFuncAttributeMaxDynamicSharedMemorySize, SMEM_BYTES);

    gru_attn_kernel<<<BLOCKS_, THREADS_, SMEM_BYTES>>>(
        xp, lenp, Wihp, Whhp, bihp, bhhp, Wfp, bfp, Wap, bap, (float*)d_out);
}